// round 3
// baseline (speedup 1.0000x reference)
#include <cuda_runtime.h>
#include <math.h>

// ---------------------------------------------------------------------------
// WeightedConformers: SchNet-style message passing + conformer readout.
//
// Key restructure: the edge filter filt(d) = ssp(g(d)@Wf1+bf1)@Wf2+bf2 is a
// function of the scalar edge distance only. We tabulate it per layer on a
// fine grid (exact fp32 evaluation at grid points, linear interpolation
// between; error ~1e-5 << 1e-3 gate) and fully fuse the edge phase:
// lerp + gather phi[a1] + multiply + vector-atomic scatter into agg[a0].
// No E x 256 intermediate ever touches DRAM.
// ---------------------------------------------------------------------------

#define N_ATOMS_C 51200
#define N_EDGES_C 524288
#define D_C       256
#define NG_C      64
#define L_C       3
#define NTAB      8192
#define DMAX      8.0f
#define NMOLS     64
#define NCONFS    20
#define MOLSZ     40

// Scratch (static device globals; no allocation anywhere).
__device__ __align__(128) float g_d[N_EDGES_C];
__device__ __align__(128) float g_r[N_ATOMS_C * D_C];
__device__ __align__(128) float g_phi[N_ATOMS_C * D_C];
__device__ __align__(128) float g_agg[N_ATOMS_C * D_C];
__device__ __align__(128) float g_hid[N_ATOMS_C * D_C];
__device__ __align__(128) float g_tab[L_C][NTAB * D_C];
__device__ __align__(128) float g_cs[NMOLS * NCONFS * D_C];
__device__ __align__(128) float g_h1[NMOLS * NCONFS * 384];
__device__ __align__(128) float g_hh[NMOLS * NCONFS * 512];
__device__ __align__(128) float g_fp[NMOLS * 512];

__device__ __forceinline__ float sspf(float x) {
    // softplus(x) - log(2), numerically stable (matches jax.nn.softplus)
    return fmaxf(x, 0.0f) + log1pf(expf(-fabsf(x))) - 0.69314718055994531f;
}

// ---------------------------------------------------------------------------
// Edge distances: d = sqrt(|xyz[a0]-xyz[a1]|^2 + 1e-12), xyz = nxyz[:,1:4]
// ---------------------------------------------------------------------------
__global__ void compute_d_k(const float4* __restrict__ nxyz,
                            const int2* __restrict__ nbr) {
    int e = blockIdx.x * blockDim.x + threadIdx.x;
    int2 ab = nbr[e];
    float4 p0 = nxyz[ab.x];
    float4 p1 = nxyz[ab.y];
    float dx = p0.y - p1.y, dy = p0.z - p1.z, dz = p0.w - p1.w;
    g_d[e] = sqrtf(dx * dx + dy * dy + dz * dz + 1e-12f);
}

// r0 = emb[z]  (float4-vectorized gather)
__global__ void gather_emb_k(const float4* __restrict__ emb,
                             const int* __restrict__ z) {
    int idx = blockIdx.x * blockDim.x + threadIdx.x;  // over N_ATOMS*64
    int a = idx >> 6, c = idx & 63;
    ((float4*)g_r)[idx] = emb[z[a] * 64 + c];
}

// ---------------------------------------------------------------------------
// Filter table: g_tab[l][i][:] = ssp(g(d_i)@Wf1[l]+bf1[l])@Wf2[l]+bf2[l]
// d_i = i * DMAX/(NTAB-1). Exact fp32 at grid points.
// ---------------------------------------------------------------------------
__global__ void build_tab_k(const float* __restrict__ Wf1, const float* __restrict__ bf1,
                            const float* __restrict__ Wf2, const float* __restrict__ bf2) {
    __shared__ float sg[NG_C];
    __shared__ float sh[D_C];
    int i = blockIdx.x, l = blockIdx.y, t = threadIdx.x;
    float dv = (float)i * (DMAX / (float)(NTAB - 1));
    if (t < NG_C) {
        float mu = (float)t * (5.0f / 63.0f);
        float u = (dv - mu) * (63.0f / 5.0f);
        sg[t] = expf(-0.5f * u * u);
    }
    __syncthreads();
    float a = bf1[l * D_C + t];
#pragma unroll 8
    for (int j = 0; j < NG_C; j++) a += sg[j] * Wf1[(l * NG_C + j) * D_C + t];
    sh[t] = sspf(a);
    __syncthreads();
    float o = bf2[l * D_C + t];
#pragma unroll 8
    for (int k = 0; k < D_C; k++) o += sh[k] * Wf2[(l * D_C + k) * D_C + t];
    g_tab[l][i * D_C + t] = o;
}

__global__ void zero_agg_k() {
    int i = blockIdx.x * blockDim.x + threadIdx.x;
    ((float4*)g_agg)[i] = make_float4(0.f, 0.f, 0.f, 0.f);
}

// ---------------------------------------------------------------------------
// Fused edge kernel (one warp per edge):
//   filt = lerp(table, d);  msg = phi[a1]*filt;  agg[a0] += msg (red.v4)
// ---------------------------------------------------------------------------
__global__ __launch_bounds__(256) void edge_k(const int2* __restrict__ nbr, int l) {
    int e = blockIdx.x * 8 + (threadIdx.x >> 5);
    int lane = threadIdx.x & 31;
    int2 ab = nbr[e];
    float t = g_d[e] * ((float)(NTAB - 1) / DMAX);
    t = fminf(t, (float)(NTAB - 1) - 0.001f);  // clamp: tail is exactly constant
    int i0 = (int)t;
    float f = t - (float)i0;
    const float4* ta = (const float4*)(g_tab[l] + i0 * D_C);
    const float4* tb = ta + (D_C / 4);
    const float4* ph = (const float4*)g_phi + ab.y * (D_C / 4);
    float* ag = g_agg + ab.x * D_C;
#pragma unroll
    for (int rep = 0; rep < 2; rep++) {
        int j = lane + rep * 32;
        float4 x0 = ta[j], x1 = tb[j], p = ph[j];
        float vx = fmaf(f, x1.x - x0.x, x0.x) * p.x;
        float vy = fmaf(f, x1.y - x0.y, x0.y) * p.y;
        float vz = fmaf(f, x1.z - x0.z, x0.z) * p.z;
        float vw = fmaf(f, x1.w - x0.w, x0.w) * p.w;
        asm volatile("red.global.add.v4.f32 [%0], {%1, %2, %3, %4};"
                     :: "l"(ag + j * 4), "f"(vx), "f"(vy), "f"(vz), "f"(vw)
                     : "memory");
    }
}

// ---------------------------------------------------------------------------
// Register-blocked fp32 SGEMM, 128x128 tile, BK=8, 256 threads, 8x8/thread.
// MODE 0: C = A@B + bias          (phi)
// MODE 1: C = ssp(A@B + bias)     (hidden of output MLP)
// MODE 2: C = Cin + A@B + bias    (residual update, Cin may alias C)
// M % 128 == 0, N % 128 == 0, K % 8 == 0 assumed.
// ---------------------------------------------------------------------------
template <int MODE>
__global__ __launch_bounds__(256) void sgemm_k(
    const float* __restrict__ A, const float* __restrict__ B,
    const float* __restrict__ bias, const float* __restrict__ Cin,
    float* __restrict__ C, int M, int N, int K) {
    __shared__ float As[8][128];
    __shared__ float Bs[8][128];
    const int t = threadIdx.x;
    const int tx = t & 15, ty = t >> 4;
    const int row0 = blockIdx.y * 128;
    const int col0 = blockIdx.x * 128;
    const int arow = t >> 1, acol = (t & 1) * 4;
    const int brow = t >> 5, bcol = (t & 31) * 4;
    const float* Aptr = A + (size_t)(row0 + arow) * K + acol;
    const float* Bptr = B + (size_t)brow * N + col0 + bcol;

    float acc[8][8];
#pragma unroll
    for (int i = 0; i < 8; i++)
#pragma unroll
        for (int j = 0; j < 8; j++) acc[i][j] = 0.f;

    float4 a_nx = *(const float4*)Aptr;
    float4 b_nx = *(const float4*)Bptr;

    for (int k0 = 0; k0 < K; k0 += 8) {
        As[acol + 0][arow] = a_nx.x;
        As[acol + 1][arow] = a_nx.y;
        As[acol + 2][arow] = a_nx.z;
        As[acol + 3][arow] = a_nx.w;
        *(float4*)&Bs[brow][bcol] = b_nx;
        __syncthreads();
        if (k0 + 8 < K) {
            a_nx = *(const float4*)(Aptr + k0 + 8);
            b_nx = *(const float4*)(Bptr + (size_t)(k0 + 8) * N);
        }
#pragma unroll
        for (int kk = 0; kk < 8; kk++) {
            float ar[8], br[8];
            *(float4*)&ar[0] = *(const float4*)&As[kk][ty * 8];
            *(float4*)&ar[4] = *(const float4*)&As[kk][ty * 8 + 4];
            *(float4*)&br[0] = *(const float4*)&Bs[kk][tx * 8];
            *(float4*)&br[4] = *(const float4*)&Bs[kk][tx * 8 + 4];
#pragma unroll
            for (int i = 0; i < 8; i++)
#pragma unroll
                for (int j = 0; j < 8; j++) acc[i][j] = fmaf(ar[i], br[j], acc[i][j]);
        }
        __syncthreads();
    }

    const float* bptr = bias + col0 + tx * 8;
#pragma unroll
    for (int i = 0; i < 8; i++) {
        int r = row0 + ty * 8 + i;
        float* cptr = C + (size_t)r * N + col0 + tx * 8;
#pragma unroll
        for (int j0 = 0; j0 < 8; j0 += 4) {
            float4 v;
            v.x = acc[i][j0 + 0] + bptr[j0 + 0];
            v.y = acc[i][j0 + 1] + bptr[j0 + 1];
            v.z = acc[i][j0 + 2] + bptr[j0 + 2];
            v.w = acc[i][j0 + 3] + bptr[j0 + 3];
            if (MODE == 1) {
                v.x = sspf(v.x); v.y = sspf(v.y); v.z = sspf(v.z); v.w = sspf(v.w);
            }
            if (MODE == 2) {
                float4 c0 = *(const float4*)(Cin + (size_t)r * N + col0 + tx * 8 + j0);
                v.x += c0.x; v.y += c0.y; v.z += c0.z; v.w += c0.w;
            }
            *(float4*)(cptr + j0) = v;
        }
    }
}

// ---------------------------------------------------------------------------
// Readout tail (all tiny)
// ---------------------------------------------------------------------------
__global__ void conf_sum_k() {
    int row = blockIdx.x, t = threadIdx.x;  // row over 1280 (mol,conf), t over D
    float s = 0.f;
#pragma unroll
    for (int i = 0; i < MOLSZ; i++) s += g_r[(row * MOLSZ + i) * D_C + t];
    g_cs[row * D_C + t] = s;
}

__global__ void mlp1_k(const float* __restrict__ mW1, const float* __restrict__ mb1) {
    __shared__ float s[D_C];
    int row = blockIdx.x, t = threadIdx.x;  // 384 threads
    if (t < D_C) s[t] = g_cs[row * D_C + t];
    __syncthreads();
    float a = mb1[t];
    for (int k = 0; k < D_C; k++) a += s[k] * mW1[k * 384 + t];
    g_h1[row * 384 + t] = sspf(a);
}

__global__ void mlp2_k(const float* __restrict__ mW2, const float* __restrict__ mb2) {
    __shared__ float s[384];
    int row = blockIdx.x, t = threadIdx.x;  // 512 threads
    if (t < 384) s[t] = g_h1[row * 384 + t];
    __syncthreads();
    float a = mb2[t];
    for (int k = 0; k < 384; k++) a += s[k] * mW2[k * 512 + t];
    g_hh[row * 512 + t] = a;
}

__global__ void fp_k(const float* __restrict__ w) {
    int m = blockIdx.x, t = threadIdx.x;  // 512 threads
    float a = 0.f;
#pragma unroll
    for (int c = 0; c < NCONFS; c++)
        a += w[m * NCONFS + c] * g_hh[(m * NCONFS + c) * 512 + t];
    g_fp[m * 512 + t] = a;
}

__global__ void readout_k(const float* __restrict__ rW1, const float* __restrict__ rb1,
                          const float* __restrict__ rW2, const float* __restrict__ rb2,
                          float* __restrict__ out) {
    __shared__ float s[512];
    __shared__ float red[256];
    int m = blockIdx.x, t = threadIdx.x;  // 256 threads
    s[t] = g_fp[m * 512 + t];
    s[t + 256] = g_fp[m * 512 + 256 + t];
    __syncthreads();
    float a = rb1[t];
    for (int j = 0; j < 512; j++) a += s[j] * rW1[j * D_C + t];
    red[t] = sspf(a) * rW2[t];
    __syncthreads();
    for (int st = 128; st > 0; st >>= 1) {
        if (t < st) red[t] += red[t + st];
        __syncthreads();
    }
    if (t == 0) out[m] = red[0] + rb2[0];
}

// ---------------------------------------------------------------------------
extern "C" void kernel_launch(void* const* d_in, const int* in_sizes, int n_in,
                              void* d_out, int out_size) {
    const float* nxyz    = (const float*)d_in[0];
    const float* weights = (const float*)d_in[1];
    const float* emb     = (const float*)d_in[2];
    const float* Wm      = (const float*)d_in[3];
    const float* bm      = (const float*)d_in[4];
    const float* Wf1     = (const float*)d_in[5];
    const float* bf1     = (const float*)d_in[6];
    const float* Wf2     = (const float*)d_in[7];
    const float* bf2     = (const float*)d_in[8];
    const float* Wo1     = (const float*)d_in[9];
    const float* bo1     = (const float*)d_in[10];
    const float* Wo2     = (const float*)d_in[11];
    const float* bo2     = (const float*)d_in[12];
    const float* mW1     = (const float*)d_in[13];
    const float* mb1     = (const float*)d_in[14];
    const float* mW2     = (const float*)d_in[15];
    const float* mb2     = (const float*)d_in[16];
    const float* rW1     = (const float*)d_in[17];
    const float* rb1     = (const float*)d_in[18];
    const float* rW2     = (const float*)d_in[19];
    const float* rb2     = (const float*)d_in[20];
    const int*   z       = (const int*)d_in[21];
    const int2*  nbr     = (const int2*)d_in[22];

    float *p_r, *p_phi, *p_agg, *p_hid;
    cudaGetSymbolAddress((void**)&p_r, g_r);
    cudaGetSymbolAddress((void**)&p_phi, g_phi);
    cudaGetSymbolAddress((void**)&p_agg, g_agg);
    cudaGetSymbolAddress((void**)&p_hid, g_hid);

    compute_d_k<<<N_EDGES_C / 256, 256>>>((const float4*)nxyz, nbr);
    gather_emb_k<<<(N_ATOMS_C * 64) / 256, 256>>>((const float4*)emb, z);
    build_tab_k<<<dim3(NTAB, L_C), 256>>>(Wf1, bf1, Wf2, bf2);

    dim3 gg(D_C / 128, N_ATOMS_C / 128);  // (2, 400)
    for (int l = 0; l < L_C; l++) {
        sgemm_k<0><<<gg, 256>>>(p_r, Wm + l * D_C * D_C, bm + l * D_C,
                                (const float*)nullptr, p_phi, N_ATOMS_C, D_C, D_C);
        zero_agg_k<<<(N_ATOMS_C * 64) / 256, 256>>>();
        edge_k<<<N_EDGES_C / 8, 256>>>(nbr, l);
        sgemm_k<1><<<gg, 256>>>(p_agg, Wo1 + l * D_C * D_C, bo1 + l * D_C,
                                (const float*)nullptr, p_hid, N_ATOMS_C, D_C, D_C);
        sgemm_k<2><<<gg, 256>>>(p_hid, Wo2 + l * D_C * D_C, bo2 + l * D_C,
                                p_r, p_r, N_ATOMS_C, D_C, D_C);
    }

    conf_sum_k<<<NMOLS * NCONFS, 256>>>();
    mlp1_k<<<NMOLS * NCONFS, 384>>>(mW1, mb1);
    mlp2_k<<<NMOLS * NCONFS, 512>>>(mW2, mb2);
    fp_k<<<NMOLS, 512>>>(weights);
    readout_k<<<NMOLS, 256>>>(rW1, rb1, rW2, rb2, (float*)d_out);
}